// round 5
// baseline (speedup 1.0000x reference)
#include <cuda_runtime.h>
#include <mma.h>
#include <math.h>

using namespace nvcuda;

#define B_   8192
#define L_   10
#define NT_  26
#define V_   200000
#define HB_  4096              // half batch

// per-row scratch: h1(512) h2(256) h3(64) T26(1664) R(416) z1(512) z2(256) = 3680
// plus padded top_W1 [512][416]
__device__ __align__(256) float g_scratch[(size_t)B_ * 3680 + 512 * 416];

// emb groups: 32 bags per block, 26*4096/32 = 3328 groups per half
#define EGROUPS 3328
// embA chunks (phase 1 hosts: botl1, botL2, botL3)
#define EA1 1000
#define EA2 1400
#define EA3 (EGROUPS - EA1 - EA2)
// embB chunks (phase 2 hosts: interactA, topL1A, topL2A, top3A)
#define EB1 1100
#define EB2 1100
#define EB3 600
#define EB4 (EGROUPS - EB1 - EB2 - EB3)

// ---------------------------------------------------------------------------
// cp.async helpers
// ---------------------------------------------------------------------------
__device__ __forceinline__ void cp16(void* smem, const void* gmem) {
    unsigned s = (unsigned)__cvta_generic_to_shared(smem);
    asm volatile("cp.async.ca.shared.global [%0], [%1], 16;\n" :: "r"(s), "l"(gmem));
}
__device__ __forceinline__ void cp_commit() { asm volatile("cp.async.commit_group;\n"); }
template<int N> __device__ __forceinline__ void cp_wait() {
    asm volatile("cp.async.wait_group %0;\n" :: "n"(N));
}

// ---------------------------------------------------------------------------
// Hybrid embedding block: 32 bags, 8 threads/bag, 2 float4 per thread per row
// -> 20 independent 16B loads in flight per thread (high MLP at low occupancy)
// ---------------------------------------------------------------------------
__device__ __forceinline__ void emb_group_block(
    const int* __restrict__ lS_i, const float* __restrict__ tables,
    float* __restrict__ T26, int half, int g, int tid)
{
    int sub = tid >> 3;                   // bag within block, 0..31
    int lane = tid & 7;                   // 8 threads per bag
    int w = g * 32 + sub;                 // bag id within half, < 26*4096
    int t = w >> 12;                      // table
    int b = (half << 12) | (w & 4095);    // batch row
    const int* idx = lS_i + (size_t)t * (B_ * L_) + (size_t)b * L_;
    const float* tab = tables + (size_t)t * (V_ * 64);
    int r[L_];
    #pragma unroll
    for (int l = 0; l < L_; l++) r[l] = idx[l];
    float4 a0 = make_float4(0.f, 0.f, 0.f, 0.f);
    float4 a1 = make_float4(0.f, 0.f, 0.f, 0.f);
    #pragma unroll
    for (int l = 0; l < L_; l++) {
        const float4* p = (const float4*)(tab + (size_t)r[l] * 64);
        float4 v0 = p[lane];
        float4 v1 = p[lane + 8];
        a0.x += v0.x; a0.y += v0.y; a0.z += v0.z; a0.w += v0.w;
        a1.x += v1.x; a1.y += v1.y; a1.z += v1.z; a1.w += v1.w;
    }
    float4* dst = (float4*)(T26 + (size_t)b * 1664 + (size_t)t * 64);
    dst[lane] = a0;
    dst[lane + 8] = a1;
}

// ---------------------------------------------------------------------------
// Bottom MLP layer 1 (hybrid): [B,13] x [512,13]^T + b, ReLU -> h1 [B,512]
// ---------------------------------------------------------------------------
__global__ void __launch_bounds__(256) botl1_kernel(
    const float* __restrict__ x, const float* __restrict__ W,
    const float* __restrict__ bias, float* __restrict__ h1,
    int mainBlocks,
    const int* __restrict__ lS_i, const float* __restrict__ tables,
    float* __restrict__ T26, int half, int gStart)
{
    if ((int)blockIdx.x >= mainBlocks) {
        emb_group_block(lS_i, tables, T26, half,
                        gStart + (int)blockIdx.x - mainBlocks, threadIdx.x);
        return;
    }
    __shared__ float Ws[512 * 13];
    __shared__ float bs[512];
    __shared__ float xs[16 * 13];
    int r0 = blockIdx.x * 16;
    for (int i = threadIdx.x; i < 512 * 13; i += 256) Ws[i] = W[i];
    for (int i = threadIdx.x; i < 512; i += 256) bs[i] = bias[i];
    for (int i = threadIdx.x; i < 16 * 13; i += 256) xs[i] = x[r0 * 13 + i];
    __syncthreads();
    #pragma unroll
    for (int cp = 0; cp < 2; cp++) {
        int c = threadIdx.x + cp * 256;
        float wreg[13];
        #pragma unroll
        for (int k = 0; k < 13; k++) wreg[k] = Ws[c * 13 + k];
        float bb = bs[c];
        #pragma unroll
        for (int r = 0; r < 16; r++) {
            float acc = bb;
            #pragma unroll
            for (int k = 0; k < 13; k++) acc = fmaf(wreg[k], xs[r * 13 + k], acc);
            h1[(size_t)(r0 + r) * 512 + c] = fmaxf(acc, 0.f);
        }
    }
}

// ---------------------------------------------------------------------------
// tf32 wmma GEMM (hybrid): out = relu(X[M,lda] @ W[N,ldw]^T + bias)
// BM=128, BN in {128, 64}. 8 warps 4x2, warp tile 32 x BN/2. dbl-buffered.
// ---------------------------------------------------------------------------
#define BK   16
#define KPAD 20

template<int BN>
__global__ void __launch_bounds__(256, 2) gemm_tf32(
    const float* __restrict__ X, int lda,
    const float* __restrict__ W, int ldw,
    const float* __restrict__ bias,
    float* __restrict__ out, int ldc, int K,
    int mainX, int mainBlocks,
    const int* __restrict__ lS_i, const float* __restrict__ tables,
    float* __restrict__ T26, int half, int gStart)
{
    if ((int)blockIdx.x >= mainBlocks) {
        emb_group_block(lS_i, tables, T26, half,
                        gStart + (int)blockIdx.x - mainBlocks, threadIdx.x);
        return;
    }
    constexpr int WTN = BN / 2;
    constexpr int FN = WTN / 16;
    __shared__ float As[2][128][KPAD];
    __shared__ float Bs[2][BN][KPAD];
    int tid = threadIdx.x;
    int warp = tid >> 5;
    int lane = tid & 31;
    int wm = warp >> 1, wn = warp & 1;
    int bx = (int)blockIdx.x % mainX, by = (int)blockIdx.x / mainX;
    int m0 = bx * 128, n0 = by * BN;

    wmma::fragment<wmma::accumulator, 16, 16, 8, float> acc[2][FN];
    #pragma unroll
    for (int i = 0; i < 2; i++)
        #pragma unroll
        for (int j = 0; j < FN; j++) wmma::fill_fragment(acc[i][j], 0.f);

    auto load_tile = [&](int buf, int k0) {
        #pragma unroll
        for (int i = tid; i < 128 * 4; i += 256) {
            int r = i >> 2, s = (i & 3) * 4;
            cp16(&As[buf][r][s], X + (size_t)(m0 + r) * lda + k0 + s);
        }
        #pragma unroll
        for (int i = tid; i < BN * 4; i += 256) {
            int r = i >> 2, s = (i & 3) * 4;
            cp16(&Bs[buf][r][s], W + (size_t)(n0 + r) * ldw + k0 + s);
        }
        cp_commit();
    };

    int nIter = K / BK;
    load_tile(0, 0);
    int buf = 0;
    for (int it = 0; it < nIter; it++) {
        if (it + 1 < nIter) { load_tile(buf ^ 1, (it + 1) * BK); cp_wait<1>(); }
        else cp_wait<0>();
        __syncthreads();
        #pragma unroll
        for (int ks = 0; ks < 2; ks++) {
            wmma::fragment<wmma::matrix_a, 16, 16, 8, wmma::precision::tf32, wmma::row_major> af[2];
            wmma::fragment<wmma::matrix_b, 16, 16, 8, wmma::precision::tf32, wmma::col_major> bf[FN];
            #pragma unroll
            for (int mi = 0; mi < 2; mi++)
                wmma::load_matrix_sync(af[mi], &As[buf][wm * 32 + mi * 16][ks * 8], KPAD);
            #pragma unroll
            for (int nj = 0; nj < FN; nj++)
                wmma::load_matrix_sync(bf[nj], &Bs[buf][wn * WTN + nj * 16][ks * 8], KPAD);
            #pragma unroll
            for (int mi = 0; mi < 2; mi++)
                #pragma unroll
                for (int nj = 0; nj < FN; nj++)
                    wmma::mma_sync(acc[mi][nj], af[mi], bf[nj], acc[mi][nj]);
        }
        __syncthreads();
        buf ^= 1;
    }

    float* es = &As[0][0][0] + warp * 16 * KPAD;
    #pragma unroll
    for (int mi = 0; mi < 2; mi++) {
        #pragma unroll
        for (int nj = 0; nj < FN; nj++) {
            wmma::store_matrix_sync(es, acc[mi][nj], KPAD, wmma::mem_row_major);
            __syncwarp();
            int r = lane >> 1, c0 = (lane & 1) * 8;
            int gm = m0 + wm * 32 + mi * 16 + r;
            int gn = n0 + wn * WTN + nj * 16 + c0;
            #pragma unroll
            for (int c = 0; c < 8; c++) {
                float v = es[r * KPAD + c0 + c] + bias[gn + c];
                out[(size_t)gm * ldc + gn + c] = fmaxf(v, 0.f);
            }
            __syncwarp();
        }
    }
}

// ---------------------------------------------------------------------------
// Dot interaction (hybrid, per half): Z = T T^T, R = [h3, tril(Z)]
// ---------------------------------------------------------------------------
#define TLD 68

__global__ void __launch_bounds__(256) interact_kernel(
    const float* __restrict__ h3, const float* __restrict__ T26,
    float* __restrict__ R, int half,
    int mainBlocks,
    const int* __restrict__ lS_i, const float* __restrict__ tables,
    float* __restrict__ T26w, int ehalf, int gStart)
{
    if ((int)blockIdx.x >= mainBlocks) {
        emb_group_block(lS_i, tables, T26w, ehalf,
                        gStart + (int)blockIdx.x - mainBlocks, threadIdx.x);
        return;
    }
    extern __shared__ float sT[];          // 8 * 32 * TLD floats
    __shared__ float sZ[8][16][KPAD];
    int tid = threadIdx.x, warp = tid >> 5, lane = tid & 31;
    int b0 = half * HB_ + blockIdx.x * 8;

    for (int idx = tid; idx < 8 * 32 * 64; idx += 256) {
        int row = idx >> 11;
        int e = idx & 2047;
        int i = e >> 6, d = e & 63;
        float v = 0.f;
        if (i == 0)       v = h3[(size_t)(b0 + row) * 64 + d];
        else if (i < 27)  v = T26[(size_t)(b0 + row) * 1664 + (i - 1) * 64 + d];
        sT[(row * 32 + i) * TLD + d] = v;
    }
    __syncthreads();

    const float* tb = sT + warp * 32 * TLD;
    wmma::fragment<wmma::accumulator, 16, 16, 8, float> z[2][2];
    #pragma unroll
    for (int i = 0; i < 2; i++)
        #pragma unroll
        for (int j = 0; j < 2; j++) wmma::fill_fragment(z[i][j], 0.f);

    #pragma unroll
    for (int ks = 0; ks < 8; ks++) {
        wmma::fragment<wmma::matrix_a, 16, 16, 8, wmma::precision::tf32, wmma::row_major> af[2];
        wmma::fragment<wmma::matrix_b, 16, 16, 8, wmma::precision::tf32, wmma::col_major> bf[2];
        #pragma unroll
        for (int ti = 0; ti < 2; ti++) {
            wmma::load_matrix_sync(af[ti], tb + (ti * 16) * TLD + ks * 8, TLD);
            wmma::load_matrix_sync(bf[ti], tb + (ti * 16) * TLD + ks * 8, TLD);
        }
        #pragma unroll
        for (int ti = 0; ti < 2; ti++)
            #pragma unroll
            for (int tj = 0; tj < 2; tj++)
                wmma::mma_sync(z[ti][tj], af[ti], bf[tj], z[ti][tj]);
    }

    float* Rb = R + (size_t)(b0 + warp) * 416;
    #pragma unroll
    for (int d = lane; d < 64; d += 32) Rb[d] = tb[d];
    if (lane == 0) Rb[415] = 0.f;

    #pragma unroll
    for (int ti = 0; ti < 2; ti++) {
        #pragma unroll
        for (int tj = 0; tj <= ti; tj++) {
            wmma::store_matrix_sync(&sZ[warp][0][0], z[ti][tj], KPAD, wmma::mem_row_major);
            __syncwarp();
            int r = lane >> 1, c0 = (lane & 1) * 8;
            int gi = ti * 16 + r;
            #pragma unroll
            for (int c = 0; c < 8; c++) {
                int gj = tj * 16 + c0 + c;
                if (gi > gj && gi >= 1 && gi <= 26)
                    Rb[64 + gi * (gi - 1) / 2 + gj] = sZ[warp][r][c0 + c];
            }
            __syncwarp();
        }
    }
}

// ---------------------------------------------------------------------------
// Pad top_W1 [512,415] -> Wp [512,416] (col 415 = 0)
// ---------------------------------------------------------------------------
__global__ void __launch_bounds__(256) padw_kernel(
    const float* __restrict__ w, float* __restrict__ wp)
{
    int i = blockIdx.x * 256 + threadIdx.x;
    if (i >= 512 * 416) return;
    int n = i / 416, c = i - n * 416;
    wp[i] = (c < 415) ? w[n * 415 + c] : 0.f;
}

// ---------------------------------------------------------------------------
// Top MLP layer 3 (hybrid, per half): sigmoid(z2 . W + b) -> out
// ---------------------------------------------------------------------------
__global__ void __launch_bounds__(256) top3_kernel(
    const float* __restrict__ z2, const float* __restrict__ W,
    const float* __restrict__ bias, float* __restrict__ out, int half,
    int mainBlocks,
    const int* __restrict__ lS_i, const float* __restrict__ tables,
    float* __restrict__ T26w, int ehalf, int gStart)
{
    if ((int)blockIdx.x >= mainBlocks) {
        emb_group_block(lS_i, tables, T26w, ehalf,
                        gStart + (int)blockIdx.x - mainBlocks, threadIdx.x);
        return;
    }
    int gw = blockIdx.x * 8 + (threadIdx.x >> 5);
    int lane = threadIdx.x & 31;
    int row = half * HB_ + gw;
    const float* zr = z2 + (size_t)row * 256;
    float acc = 0.f;
    #pragma unroll
    for (int u = 0; u < 8; u++) acc = fmaf(zr[lane + 32 * u], W[lane + 32 * u], acc);
    #pragma unroll
    for (int o = 16; o > 0; o >>= 1) acc += __shfl_xor_sync(0xffffffffu, acc, o);
    if (lane == 0) out[row] = 1.f / (1.f + expf(-(acc + bias[0])));
}

// ---------------------------------------------------------------------------
extern "C" void kernel_launch(void* const* d_in, const int* in_sizes, int n_in,
                              void* d_out, int out_size)
{
    const float* x    = (const float*)d_in[0];
    const int*   lS_i = (const int*)d_in[1];
    const float* emb  = (const float*)d_in[3];
    const float* bW1  = (const float*)d_in[4];
    const float* bb1  = (const float*)d_in[5];
    const float* bW2  = (const float*)d_in[6];
    const float* bb2  = (const float*)d_in[7];
    const float* bW3  = (const float*)d_in[8];
    const float* bb3  = (const float*)d_in[9];
    const float* tW1  = (const float*)d_in[10];
    const float* tb1  = (const float*)d_in[11];
    const float* tW2  = (const float*)d_in[12];
    const float* tb2  = (const float*)d_in[13];
    const float* tW3  = (const float*)d_in[14];
    const float* tb3  = (const float*)d_in[15];
    float* out = (float*)d_out;

    float* base;
    cudaGetSymbolAddress((void**)&base, g_scratch);
    float* h1  = base;                        // [B,512]
    float* h2  = h1  + (size_t)B_ * 512;      // [B,256]
    float* h3  = h2  + (size_t)B_ * 256;      // [B,64]
    float* T26 = h3  + (size_t)B_ * 64;       // [B,26,64]
    float* R   = T26 + (size_t)B_ * 1664;     // [B,416]
    float* z1  = R   + (size_t)B_ * 416;      // [B,512]
    float* z2  = z1  + (size_t)B_ * 512;      // [B,256]
    float* Wp  = z2  + (size_t)B_ * 256;      // [512,416]

    cudaFuncSetAttribute(interact_kernel,
                         cudaFuncAttributeMaxDynamicSharedMemorySize,
                         8 * 32 * TLD * (int)sizeof(float));
    int ismem = 8 * 32 * TLD * sizeof(float);

    padw_kernel<<<(512 * 416 + 255) / 256, 256>>>(tW1, Wp);

    // ---- phase 1: bottom MLP (full batch), hosting embA (half 0) ----
    botl1_kernel<<<512 + EA1, 256>>>(x, bW1, bb1, h1,
                                     512, lS_i, emb, T26, 0, 0);
    gemm_tf32<128><<<128 + EA2, 256>>>(h1, 512, bW2, 512, bb2, h2, 256, 512,
                                       64, 128, lS_i, emb, T26, 0, EA1);
    gemm_tf32<64><<<64 + EA3, 256>>>(h2, 256, bW3, 256, bb3, h3, 64, 256,
                                     64, 64, lS_i, emb, T26, 0, EA1 + EA2);

    // ---- phase 2: half 0 interact+top, hosting embB (half 1) ----
    interact_kernel<<<512 + EB1, 256, ismem>>>(h3, T26, R, 0,
                                               512, lS_i, emb, T26, 1, 0);
    gemm_tf32<128><<<128 + EB2, 256>>>(R, 416, Wp, 416, tb1,
                                       z1, 512, 416,
                                       32, 128, lS_i, emb, T26, 1, EB1);
    gemm_tf32<128><<<64 + EB3, 256>>>(z1, 512, tW2, 512, tb2, z2, 256, 512,
                                      32, 64, lS_i, emb, T26, 1, EB1 + EB2);
    top3_kernel<<<512 + EB4, 256>>>(z2, tW3, tb3, out, 0,
                                    512, lS_i, emb, T26, 1, EB1 + EB2 + EB3);

    // ---- phase 3: half 1 interact+top ----
    interact_kernel<<<512, 256, ismem>>>(h3, T26, R, 1,
                                         512, lS_i, emb, T26, 1, 0);
    gemm_tf32<128><<<128, 256>>>(R + (size_t)HB_ * 416, 416, Wp, 416, tb1,
                                 z1 + (size_t)HB_ * 512, 512, 416,
                                 32, 128, lS_i, emb, T26, 1, 0);
    gemm_tf32<128><<<64, 256>>>(z1 + (size_t)HB_ * 512, 512, tW2, 512, tb2,
                                z2 + (size_t)HB_ * 256, 256, 512,
                                32, 64, lS_i, emb, T26, 1, 0);
    top3_kernel<<<512, 256>>>(z2, tW3, tb3, out, 1,
                              512, lS_i, emb, T26, 1, 0);
}